// round 2
// baseline (speedup 1.0000x reference)
#include <cuda_runtime.h>
#include <math.h>

// Problem dims
#define BATCH 8
#define ENS   16
#define NCIN  64
#define NCH   64
#define HW    4096
#define NBI   (BATCH*ENS)          // 128
#define NELEM ((size_t)NBI*NCH*HW) // 33,554,432

// Scratch (static device arrays -- allocation-free)
__device__ float g_V[NELEM];
__device__ float g_K[NELEM];
__device__ float g_Q[NELEM];
__device__ float g_Wgt[BATCH*NCH*ENS*ENS]; // softmaxed weights [b,c,i,j]

__device__ __forceinline__ float selu_f(float x) {
    const float scale = 1.0507009873554805f;
    const float alpha = 1.6732632423543772f;
    return x > 0.f ? scale * x : scale * alpha * expm1f(x);
}

// ---------------------------------------------------------------------------
// Kernel 1: fused 3-conv.  For each (b,i): Out[192,4096] = W3[192,64] @ X[64,4096]
// Rows 0..63  -> V (bias only)
// Rows 64..127-> K (bias + selu)
// Rows 128..191-> Q (bias + selu)
// Block: 256 threads, computes [192 x 64] tile, loops NCT col-tiles.
// ---------------------------------------------------------------------------
#define ROWS3 192
#define COLT  64
#define NCT   4

__global__ __launch_bounds__(256, 2)
void conv3_kernel(const float* __restrict__ x,
                  const float* __restrict__ Wv, const float* __restrict__ bv,
                  const float* __restrict__ Wk, const float* __restrict__ bk,
                  const float* __restrict__ Wq, const float* __restrict__ bq)
{
    extern __shared__ float smem[];
    float* Wt = smem;               // [64][192]  W transposed: Wt[k*192 + r]
    float* Xs = smem + 64 * ROWS3;  // [64][64]

    const int tid = threadIdx.x;
    const int bi  = blockIdx.y;     // 0..127 (b*16+i)

    // Load fused weight matrix, k-major so row-fragments are contiguous
    for (int idx = tid; idx < 64 * ROWS3; idx += 256) {
        int k = idx / ROWS3;
        int r = idx - k * ROWS3;
        float w;
        if (r < 64)       w = Wv[r * NCIN + k];
        else if (r < 128) w = Wk[(r - 64) * NCIN + k];
        else              w = Wq[(r - 128) * NCIN + k];
        Wt[idx] = w;
    }

    const int tx = tid & 15;   // col group: 4 cols
    const int ty = tid >> 4;   // row group: 12 rows

    const float* xb   = x   + (size_t)bi * NCIN * HW;
    float* outV = g_V + (size_t)bi * NCH * HW;
    float* outK = g_K + (size_t)bi * NCH * HW;
    float* outQ = g_Q + (size_t)bi * NCH * HW;

    for (int ct = 0; ct < NCT; ct++) {
        const int col0 = (blockIdx.x * NCT + ct) * COLT;
        __syncthreads();
        // Stage X tile [64 rows (a) x 64 cols (hw)]
        for (int idx = tid; idx < 64 * COLT / 4; idx += 256) {
            int a  = idx >> 4;
            int cc = (idx & 15) * 4;
            *(float4*)&Xs[a * COLT + cc] =
                *(const float4*)&xb[(size_t)a * HW + col0 + cc];
        }
        __syncthreads();

        float acc[12][4];
        #pragma unroll
        for (int r = 0; r < 12; r++)
            #pragma unroll
            for (int c = 0; c < 4; c++) acc[r][c] = 0.f;

        #pragma unroll 4
        for (int k = 0; k < 64; k++) {
            float4 b4 = *(const float4*)&Xs[k * COLT + tx * 4];
            float4 a0 = *(const float4*)&Wt[k * ROWS3 + ty * 12];
            float4 a1 = *(const float4*)&Wt[k * ROWS3 + ty * 12 + 4];
            float4 a2 = *(const float4*)&Wt[k * ROWS3 + ty * 12 + 8];
            float af[12] = {a0.x,a0.y,a0.z,a0.w, a1.x,a1.y,a1.z,a1.w,
                            a2.x,a2.y,a2.z,a2.w};
            float bf[4]  = {b4.x, b4.y, b4.z, b4.w};
            #pragma unroll
            for (int r = 0; r < 12; r++)
                #pragma unroll
                for (int c = 0; c < 4; c++)
                    acc[r][c] += af[r] * bf[c];
        }

        // Epilogue: bias (+selu for K/Q), vectorized store
        #pragma unroll
        for (int r = 0; r < 12; r++) {
            int row = ty * 12 + r;
            float4 o;
            if (row < 64) {
                float bb = __ldg(&bv[row]);
                o.x = acc[r][0] + bb; o.y = acc[r][1] + bb;
                o.z = acc[r][2] + bb; o.w = acc[r][3] + bb;
                *(float4*)&outV[(size_t)row * HW + col0 + tx * 4] = o;
            } else if (row < 128) {
                int c = row - 64;
                float bb = __ldg(&bk[c]);
                o.x = selu_f(acc[r][0] + bb); o.y = selu_f(acc[r][1] + bb);
                o.z = selu_f(acc[r][2] + bb); o.w = selu_f(acc[r][3] + bb);
                *(float4*)&outK[(size_t)c * HW + col0 + tx * 4] = o;
            } else {
                int c = row - 128;
                float bb = __ldg(&bq[c]);
                o.x = selu_f(acc[r][0] + bb); o.y = selu_f(acc[r][1] + bb);
                o.z = selu_f(acc[r][2] + bb); o.w = selu_f(acc[r][3] + bb);
                *(float4*)&outQ[(size_t)c * HW + col0 + tx * 4] = o;
            }
        }
    }
}

// ---------------------------------------------------------------------------
// Kernel 2: gram + softmax.  One block per (b,c).
// dots[i][j] = sum_hw K[b,i,c,hw] * Q[b,j,c,hw]; softmax over i; store weights.
// 128 threads: warp jg (0..3) owns j = jg*4..jg*4+3; lanes stride hw by float4.
// ---------------------------------------------------------------------------
__global__ __launch_bounds__(128)
void gram_softmax_kernel()
{
    const int c = blockIdx.x;   // 0..63
    const int b = blockIdx.y;   // 0..7
    const int tid  = threadIdx.x;
    const int jg   = tid >> 5;  // warp id
    const int lane = tid & 31;

    const float* Kb = g_K + ((size_t)b * ENS * NCH + c) * HW; // + i*NCH*HW
    const float* Qb = g_Q + ((size_t)b * ENS * NCH + c) * HW; // + j*NCH*HW

    float acc[16][4];
    #pragma unroll
    for (int i = 0; i < 16; i++)
        #pragma unroll
        for (int jj = 0; jj < 4; jj++) acc[i][jj] = 0.f;

    for (int it = 0; it < HW / 128; it++) {    // 32 iterations
        const int pos = (it * 32 + lane) * 4;
        float4 q[4];
        #pragma unroll
        for (int jj = 0; jj < 4; jj++) {
            int j = jg * 4 + jj;
            q[jj] = *(const float4*)&Qb[(size_t)j * NCH * HW + pos];
        }
        #pragma unroll
        for (int i = 0; i < 16; i++) {
            float4 k4 = *(const float4*)&Kb[(size_t)i * NCH * HW + pos];
            #pragma unroll
            for (int jj = 0; jj < 4; jj++) {
                acc[i][jj] += k4.x * q[jj].x + k4.y * q[jj].y
                            + k4.z * q[jj].z + k4.w * q[jj].w;
            }
        }
    }

    __shared__ float sdots[16][16];
    #pragma unroll
    for (int i = 0; i < 16; i++)
        #pragma unroll
        for (int jj = 0; jj < 4; jj++) {
            float v = acc[i][jj];
            #pragma unroll
            for (int off = 16; off > 0; off >>= 1)
                v += __shfl_xor_sync(0xffffffffu, v, off);
            if (lane == 0) sdots[i][jg * 4 + jj] = v;
        }
    __syncthreads();

    if (tid < 16) {
        const int j = tid;
        float m = -INFINITY;
        #pragma unroll
        for (int i = 0; i < 16; i++) m = fmaxf(m, sdots[i][j]);
        float e[16], s = 0.f;
        #pragma unroll
        for (int i = 0; i < 16; i++) { e[i] = expf(sdots[i][j] - m); s += e[i]; }
        const float inv = 1.f / s;
        #pragma unroll
        for (int i = 0; i < 16; i++)
            g_Wgt[(((size_t)b * NCH + c) * ENS + i) * ENS + j] = e[i] * inv;
    }
}

// ---------------------------------------------------------------------------
// Kernel 3: mix + selu.  out[b,j,c,hw] = selu( sum_i w[b,c,i,j] * V[b,i,c,hw] )
// (mean-centering cancels because softmax columns sum to 1)
// Grid: (HW/512, NCH, BATCH); 256 threads, float2 per thread.
// ---------------------------------------------------------------------------
__global__ __launch_bounds__(256)
void mix_kernel(float* __restrict__ out)
{
    const int tile = blockIdx.x;
    const int c    = blockIdx.y;
    const int b    = blockIdx.z;
    const int tid  = threadIdx.x;

    __shared__ float ws[16][16];   // ws[i][j]
    ws[tid >> 4][tid & 15] = g_Wgt[((size_t)b * NCH + c) * 256 + tid];
    __syncthreads();

    const int pos = tile * 512 + tid * 2;
    const float* Vb = g_V + ((size_t)b * ENS * NCH + c) * HW + pos;
    float*       ob = out + ((size_t)b * ENS * NCH + c) * HW + pos;

    float2 v[16];
    #pragma unroll
    for (int i = 0; i < 16; i++)
        v[i] = *(const float2*)&Vb[(size_t)i * NCH * HW];

    #pragma unroll
    for (int j = 0; j < 16; j++) {
        float sx = 0.f, sy = 0.f;
        #pragma unroll
        for (int i = 0; i < 16; i++) {
            float w = ws[i][j];
            sx += w * v[i].x;
            sy += w * v[i].y;
        }
        float2 o; o.x = selu_f(sx); o.y = selu_f(sy);
        *(float2*)&ob[(size_t)j * NCH * HW] = o;
    }
}

// ---------------------------------------------------------------------------
extern "C" void kernel_launch(void* const* d_in, const int* in_sizes, int n_in,
                              void* d_out, int out_size)
{
    const float* x  = (const float*)d_in[0];
    const float* Wv = (const float*)d_in[1];
    const float* bv = (const float*)d_in[2];
    const float* Wk = (const float*)d_in[3];
    const float* bk = (const float*)d_in[4];
    const float* Wq = (const float*)d_in[5];
    const float* bq = (const float*)d_in[6];
    float* out = (float*)d_out;

    const int smem_bytes = (64 * ROWS3 + 64 * COLT) * (int)sizeof(float); // 64 KB
    cudaFuncSetAttribute(conv3_kernel,
                         cudaFuncAttributeMaxDynamicSharedMemorySize, smem_bytes);

    dim3 g1(64 / NCT, NBI);          // (16, 128)
    conv3_kernel<<<g1, 256, smem_bytes>>>(x, Wv, bv, Wk, bk, Wq, bq);

    dim3 g2(NCH, BATCH);             // (64, 8)
    gram_softmax_kernel<<<g2, 128>>>();

    dim3 g3(HW / 512, NCH, BATCH);   // (8, 64, 8)
    mix_kernel<<<g3, 256>>>(out);
}